// round 2
// baseline (speedup 1.0000x reference)
#include <cuda_runtime.h>

// out[b, m] = sum_r inputs[b, r] * pmap[r, m]
// pmap has exactly one nonzero per column -> gather:
//   out[b, m] = inputs[b, idx[m]] * val[m]

#define C_IN    5120
#define N_MOVES 1858
#define N_PAIRS (N_MOVES / 2)   // 929 (N_MOVES is even)

// Packed gather map: g_map[m] = { row index, float bits of value }.
// Zero-initialized at module load => unwritten columns give idx=0, val=0.0f,
// which matches the reference (all-zero column -> 0 output). build_map_kernel
// rewrites the same values every call, so kernel_launch stays deterministic.
__device__ __align__(16) int2 g_map[N_MOVES];

// ---------------------------------------------------------------------------
// Kernel A: scan pmap [C_IN, N_MOVES] row-major for the one nonzero per column.
// Each thread owns 2 adjacent columns (one float2 load per row -> coalesced
// 8B accesses across the warp). grid.y chunks the row dimension so the 38 MB
// scan is spread across the chip. Exactly one nonzero per column => no races.
// ---------------------------------------------------------------------------
#define ROWS_PER_CHUNK 64
#define BUILD_THREADS  256

__global__ __launch_bounds__(BUILD_THREADS)
void build_map_kernel(const float* __restrict__ pmap) {
    int p = blockIdx.x * blockDim.x + threadIdx.x;   // pair of columns
    if (p >= N_PAIRS) return;
    int r0   = blockIdx.y * ROWS_PER_CHUNK;
    int rend = min(r0 + ROWS_PER_CHUNK, C_IN);

    const char* base = (const char*)pmap + (size_t)p * 8;
    #pragma unroll 4
    for (int r = r0; r < rend; r++) {
        float2 v = *(const float2*)(base + (size_t)r * (N_MOVES * 4));
        if (v.x != 0.0f) g_map[2 * p]     = make_int2(r, __float_as_int(v.x));
        if (v.y != 0.0f) g_map[2 * p + 1] = make_int2(r, __float_as_int(v.y));
    }
}

// ---------------------------------------------------------------------------
// Kernel B: one CTA per batch row. Stage the 5120-float (20 KB) row in SMEM
// via float4 (coalesced), then gather 929 move-pairs with float2 stores.
// Map entries are int4 loads (two packed moves) that stay L1-resident.
// ---------------------------------------------------------------------------
#define GATHER_THREADS 256

__global__ __launch_bounds__(GATHER_THREADS)
void gather_kernel(const float* __restrict__ in, float* __restrict__ out) {
    __shared__ float row[C_IN];

    const int b = blockIdx.x;
    const float4* __restrict__ src = reinterpret_cast<const float4*>(in + (size_t)b * C_IN);
    float4* dst = reinterpret_cast<float4*>(row);

    #pragma unroll
    for (int i = threadIdx.x; i < C_IN / 4; i += GATHER_THREADS) {
        dst[i] = src[i];
    }
    __syncthreads();

    float2* __restrict__ o2 = reinterpret_cast<float2*>(out + (size_t)b * N_MOVES);
    const int4* __restrict__ map4 = reinterpret_cast<const int4*>(g_map);

    #pragma unroll 4
    for (int p = threadIdx.x; p < N_PAIRS; p += GATHER_THREADS) {
        int4 mp = map4[p];  // {idx0, val0_bits, idx1, val1_bits}
        float2 r;
        r.x = row[mp.x] * __int_as_float(mp.y);
        r.y = row[mp.z] * __int_as_float(mp.w);
        o2[p] = r;
    }
}

// ---------------------------------------------------------------------------
extern "C" void kernel_launch(void* const* d_in, const int* in_sizes, int n_in,
                              void* d_out, int out_size) {
    const float* inputs = (const float*)d_in[0];   // [B, 80, 8, 8] = [B, 5120]
    const float* pmap   = (const float*)d_in[1];   // [5120, 1858]
    float* out          = (float*)d_out;           // [B, 1858]

    const int B = in_sizes[0] / C_IN;

    dim3 bgrid((N_PAIRS + BUILD_THREADS - 1) / BUILD_THREADS,
               (C_IN + ROWS_PER_CHUNK - 1) / ROWS_PER_CHUNK);
    build_map_kernel<<<bgrid, BUILD_THREADS>>>(pmap);

    gather_kernel<<<B, GATHER_THREADS>>>(inputs, out);
}

// round 3
// speedup vs baseline: 1.1728x; 1.1728x over previous
#include <cuda_runtime.h>

// out[b, m] = sum_r inputs[b, r] * pmap[r, m]
// pmap has exactly one nonzero per column -> gather:
//   out[b, m] = inputs[b, idx[m]] * val[m]

#define C_IN    5120
#define N_MOVES 1858
#define N_PAIRS (N_MOVES / 2)   // 929 (N_MOVES is even)

// Packed gather map: g_map[m] = { row index, float bits of value }.
// Zero-initialized at module load => unwritten columns give idx=0, val=0.0f,
// which matches the reference (all-zero column -> 0 output). build_map_kernel
// rewrites the same values every call, so kernel_launch stays deterministic.
__device__ __align__(16) int2 g_map[N_MOVES];

// ---------------------------------------------------------------------------
// Kernel A: scan pmap [C_IN, N_MOVES] row-major for the one nonzero per column.
// Each thread owns 2 adjacent columns (one float2 load per row -> coalesced
// 8B accesses across the warp). ROWS_PER_CHUNK=8, fully unrolled => 8
// independent in-flight loads per thread (MLP=8) and 2560 CTAs, making the
// 38 MB scan bandwidth-bound instead of latency-bound.
// Exactly one nonzero per column => no write races.
// ---------------------------------------------------------------------------
#define ROWS_PER_CHUNK 8
#define BUILD_THREADS  256

__global__ __launch_bounds__(BUILD_THREADS)
void build_map_kernel(const float* __restrict__ pmap) {
    int p = blockIdx.x * blockDim.x + threadIdx.x;   // pair of columns
    if (p >= N_PAIRS) return;
    const int r0 = blockIdx.y * ROWS_PER_CHUNK;      // C_IN % 8 == 0

    const char* base = (const char*)pmap + (size_t)p * 8
                     + (size_t)r0 * (N_MOVES * 4);

    // Issue all 8 loads independently (streaming: pmap has no reuse).
    float2 v[ROWS_PER_CHUNK];
    #pragma unroll
    for (int i = 0; i < ROWS_PER_CHUNK; i++) {
        v[i] = __ldcs((const float2*)(base + (size_t)i * (N_MOVES * 4)));
    }
    #pragma unroll
    for (int i = 0; i < ROWS_PER_CHUNK; i++) {
        if (v[i].x != 0.0f) g_map[2 * p]     = make_int2(r0 + i, __float_as_int(v[i].x));
        if (v[i].y != 0.0f) g_map[2 * p + 1] = make_int2(r0 + i, __float_as_int(v[i].y));
    }
}

// ---------------------------------------------------------------------------
// Kernel B: one CTA per batch row. Stage the 5120-float (20 KB) row in SMEM
// via float4 (coalesced, streaming), then gather 929 move-pairs with float2
// streaming stores. Map entries are int4 loads (two packed moves) with L2
// reuse across all 8192 CTAs.
// ---------------------------------------------------------------------------
#define GATHER_THREADS 256

__global__ __launch_bounds__(GATHER_THREADS)
void gather_kernel(const float* __restrict__ in, float* __restrict__ out) {
    __shared__ float row[C_IN];

    const int b = blockIdx.x;
    const float4* __restrict__ src = reinterpret_cast<const float4*>(in + (size_t)b * C_IN);
    float4* dst = reinterpret_cast<float4*>(row);

    #pragma unroll
    for (int i = threadIdx.x; i < C_IN / 4; i += GATHER_THREADS) {
        dst[i] = __ldcs(&src[i]);   // read-once stream: evict-first
    }
    __syncthreads();

    float2* __restrict__ o2 = reinterpret_cast<float2*>(out + (size_t)b * N_MOVES);
    const int4* __restrict__ map4 = reinterpret_cast<const int4*>(g_map);

    #pragma unroll 4
    for (int p = threadIdx.x; p < N_PAIRS; p += GATHER_THREADS) {
        int4 mp = __ldg(&map4[p]);  // {idx0, val0_bits, idx1, val1_bits}
        float2 r;
        r.x = row[mp.x] * __int_as_float(mp.y);
        r.y = row[mp.z] * __int_as_float(mp.w);
        __stcs(&o2[p], r);          // write-once stream: evict-first
    }
}

// ---------------------------------------------------------------------------
extern "C" void kernel_launch(void* const* d_in, const int* in_sizes, int n_in,
                              void* d_out, int out_size) {
    const float* inputs = (const float*)d_in[0];   // [B, 80, 8, 8] = [B, 5120]
    const float* pmap   = (const float*)d_in[1];   // [5120, 1858]
    float* out          = (float*)d_out;           // [B, 1858]

    const int B = in_sizes[0] / C_IN;

    dim3 bgrid((N_PAIRS + BUILD_THREADS - 1) / BUILD_THREADS,
               C_IN / ROWS_PER_CHUNK);
    build_map_kernel<<<bgrid, BUILD_THREADS>>>(pmap);

    gather_kernel<<<B, GATHER_THREADS>>>(inputs, out);
}

// round 4
// speedup vs baseline: 1.1784x; 1.0047x over previous
#include <cuda_runtime.h>

// out[b, m] = sum_r inputs[b, r] * pmap[r, m]
// pmap has exactly one nonzero per column -> gather:
//   out[b, m] = inputs[b, idx[m]] * val[m]

#define C_IN    5120
#define N_MOVES 1858
#define N_PAIRS (N_MOVES / 2)          // 929
#define TOTAL_ELEMS (C_IN * N_MOVES)   // 9,512,960 (divisible by 4)
#define TOTAL_V4    (TOTAL_ELEMS / 4)  // 2,378,240

// Packed gather map: g_map[m] = { row index, float bits of value }.
// Zero-initialized at module load => unwritten columns give idx=0, val=0.0f,
// which matches the reference (all-zero column -> 0 output). build_map_kernel
// rewrites the same values every call, so kernel_launch stays deterministic.
__device__ __align__(16) int2 g_map[N_MOVES];

// ---------------------------------------------------------------------------
// Kernel A: flat scan of pmap for nonzeros. pmap base is 16B-aligned and the
// total element count is divisible by 4, so the whole tensor streams through
// as perfectly-coalesced float4 loads (the 2-D view has a 7432B row stride
// that blocks 128-bit access). (r, m) is recomputed from the flat index only
// on the ~1858 nonzero hits. 8 independent loads per thread (MLP=8).
// Exactly one nonzero per column => no write races.
// ---------------------------------------------------------------------------
#define BUILD_THREADS 256
#define V4_PER_THREAD 8
#define V4_PER_BLOCK  (BUILD_THREADS * V4_PER_THREAD)   // 2048

__global__ __launch_bounds__(BUILD_THREADS)
void build_map_kernel(const float4* __restrict__ pmap4) {
    const int base = blockIdx.x * V4_PER_BLOCK + threadIdx.x;

    float4 v[V4_PER_THREAD];
    int    idx[V4_PER_THREAD];
    #pragma unroll
    for (int i = 0; i < V4_PER_THREAD; i++) {
        idx[i] = base + i * BUILD_THREADS;
        if (idx[i] < TOTAL_V4) v[i] = __ldcs(&pmap4[idx[i]]);
        else v[i] = make_float4(0.f, 0.f, 0.f, 0.f);
    }

    #pragma unroll
    for (int i = 0; i < V4_PER_THREAD; i++) {
        // Fast reject: almost every float4 is all-zero.
        if (v[i].x != 0.0f || v[i].y != 0.0f || v[i].z != 0.0f || v[i].w != 0.0f) {
            const float vv[4] = { v[i].x, v[i].y, v[i].z, v[i].w };
            #pragma unroll
            for (int c = 0; c < 4; c++) {
                if (vv[c] != 0.0f) {
                    int e = idx[i] * 4 + c;
                    int r = e / N_MOVES;            // const-div -> mul.hi
                    int m = e - r * N_MOVES;
                    g_map[m] = make_int2(r, __float_as_int(vv[c]));
                }
            }
        }
    }
}

// ---------------------------------------------------------------------------
// Kernel B: one CTA per batch row. Stage the 5120-float (20 KB) row in SMEM
// via float4 (coalesced, streaming), then gather 929 move-pairs with float2
// streaming stores. Map entries are int4 loads (two packed moves) with L2
// reuse across all 8192 CTAs.
// ---------------------------------------------------------------------------
#define GATHER_THREADS 256

__global__ __launch_bounds__(GATHER_THREADS)
void gather_kernel(const float* __restrict__ in, float* __restrict__ out) {
    __shared__ float row[C_IN];

    const int b = blockIdx.x;
    const float4* __restrict__ src = reinterpret_cast<const float4*>(in + (size_t)b * C_IN);
    float4* dst = reinterpret_cast<float4*>(row);

    #pragma unroll
    for (int i = threadIdx.x; i < C_IN / 4; i += GATHER_THREADS) {
        dst[i] = __ldcs(&src[i]);   // read-once stream: evict-first
    }
    __syncthreads();

    float2* __restrict__ o2 = reinterpret_cast<float2*>(out + (size_t)b * N_MOVES);
    const int4* __restrict__ map4 = reinterpret_cast<const int4*>(g_map);

    #pragma unroll 4
    for (int p = threadIdx.x; p < N_PAIRS; p += GATHER_THREADS) {
        int4 mp = __ldg(&map4[p]);  // {idx0, val0_bits, idx1, val1_bits}
        float2 r;
        r.x = row[mp.x] * __int_as_float(mp.y);
        r.y = row[mp.z] * __int_as_float(mp.w);
        __stcs(&o2[p], r);          // write-once stream: evict-first
    }
}

// ---------------------------------------------------------------------------
extern "C" void kernel_launch(void* const* d_in, const int* in_sizes, int n_in,
                              void* d_out, int out_size) {
    const float* inputs = (const float*)d_in[0];   // [B, 80, 8, 8] = [B, 5120]
    const float* pmap   = (const float*)d_in[1];   // [5120, 1858]
    float* out          = (float*)d_out;           // [B, 1858]

    const int B = in_sizes[0] / C_IN;

    const int build_blocks = (TOTAL_V4 + V4_PER_BLOCK - 1) / V4_PER_BLOCK;  // 1162
    build_map_kernel<<<build_blocks, BUILD_THREADS>>>(
        reinterpret_cast<const float4*>(pmap));

    gather_kernel<<<B, GATHER_THREADS>>>(inputs, out);
}

// round 5
// speedup vs baseline: 1.2466x; 1.0579x over previous
#include <cuda_runtime.h>
#include <cstdint>

// out[b, m] = sum_r inputs[b, r] * pmap[r, m]
// pmap has exactly one nonzero per column -> gather:
//   out[b, m] = inputs[b, idx[m]] * val[m]

#define C_IN      5120
#define N_MOVES   1858
#define N_PAIRS   (N_MOVES / 2)          // 929
#define ROW_BYTES (C_IN * 4)             // 20480
#define TOTAL_ELEMS (C_IN * N_MOVES)     // 9,512,960
#define TOTAL_V4    (TOTAL_ELEMS / 4)    // 2,378,240

// Packed gather map: g_map[m] = { row index, float bits of value }.
// Zero-initialized at module load => unwritten columns give idx=0, val=0.0f
// (matches reference for an all-zero column). build_map_kernel rewrites the
// same values every call => deterministic.
__device__ __align__(16) int2 g_map[N_MOVES];

// ---------------------------------------------------------------------------
// Kernel A: flat float4 scan of pmap for nonzeros (perfectly coalesced;
// the 2-D row stride 7432B would block 128-bit loads). (r, m) recovered from
// the flat index only on the ~1858 hits. MLP=8 per thread.
// ---------------------------------------------------------------------------
#define BUILD_THREADS 256
#define V4_PER_THREAD 8
#define V4_PER_BLOCK  (BUILD_THREADS * V4_PER_THREAD)   // 2048

__global__ __launch_bounds__(BUILD_THREADS)
void build_map_kernel(const float4* __restrict__ pmap4) {
    const int base = blockIdx.x * V4_PER_BLOCK + threadIdx.x;

    float4 v[V4_PER_THREAD];
    int    idx[V4_PER_THREAD];
    #pragma unroll
    for (int i = 0; i < V4_PER_THREAD; i++) {
        idx[i] = base + i * BUILD_THREADS;
        if (idx[i] < TOTAL_V4) v[i] = __ldcs(&pmap4[idx[i]]);
        else v[i] = make_float4(0.f, 0.f, 0.f, 0.f);
    }

    #pragma unroll
    for (int i = 0; i < V4_PER_THREAD; i++) {
        if (v[i].x != 0.0f || v[i].y != 0.0f || v[i].z != 0.0f || v[i].w != 0.0f) {
            const float vv[4] = { v[i].x, v[i].y, v[i].z, v[i].w };
            #pragma unroll
            for (int c = 0; c < 4; c++) {
                if (vv[c] != 0.0f) {
                    int e = idx[i] * 4 + c;
                    int r = e / N_MOVES;            // const-div -> mul.hi
                    int m = e - r * N_MOVES;
                    g_map[m] = make_int2(r, __float_as_int(vv[c]));
                }
            }
        }
    }
}

// ---------------------------------------------------------------------------
// Kernel B: one CTA per batch row.
//   1. thread 0 kicks a 20KB cp.async.bulk (TMA) of the row into SMEM
//   2. ALL threads preload their map entries (int4, L2-resident) into regs
//      while the bulk copy is in flight
//   3. mbarrier wait, then pure LDS gather + float2 streaming stores
// ---------------------------------------------------------------------------
#define GATHER_THREADS 256
#define TAIL_PAIRS (N_PAIRS - 3 * GATHER_THREADS)   // 161

__global__ __launch_bounds__(GATHER_THREADS)
void gather_kernel(const float* __restrict__ in, float* __restrict__ out) {
    __shared__ __align__(16) float row[C_IN];
    __shared__ __align__(8) uint64_t mbar;

    const int tid = threadIdx.x;
    const int b   = blockIdx.x;

    uint32_t row_sa, mbar_sa;
    asm("{ .reg .u64 t; cvta.to.shared.u64 t, %1; cvt.u32.u64 %0, t; }"
        : "=r"(row_sa) : "l"((const void*)row));
    asm("{ .reg .u64 t; cvta.to.shared.u64 t, %1; cvt.u32.u64 %0, t; }"
        : "=r"(mbar_sa) : "l"((const void*)&mbar));

    if (tid == 0) {
        asm volatile("mbarrier.init.shared.b64 [%0], 1;" :: "r"(mbar_sa) : "memory");
    }
    __syncthreads();

    if (tid == 0) {
        asm volatile("mbarrier.arrive.expect_tx.shared.b64 _, [%0], %1;"
                     :: "r"(mbar_sa), "r"((uint32_t)ROW_BYTES) : "memory");
        asm volatile(
            "cp.async.bulk.shared::cta.global.mbarrier::complete_tx::bytes "
            "[%0], [%1], %2, [%3];"
            :: "r"(row_sa), "l"(in + (size_t)b * C_IN),
               "r"((uint32_t)ROW_BYTES), "r"(mbar_sa)
            : "memory");
    }

    // Map preload overlaps the bulk copy (independent of staged data).
    const int4* __restrict__ map4 = reinterpret_cast<const int4*>(g_map);
    int4 mp0 = __ldg(&map4[tid]);
    int4 mp1 = __ldg(&map4[tid + GATHER_THREADS]);
    int4 mp2 = __ldg(&map4[tid + 2 * GATHER_THREADS]);
    int4 mp3 = make_int4(0, 0, 0, 0);
    const bool has3 = tid < TAIL_PAIRS;
    if (has3) mp3 = __ldg(&map4[tid + 3 * GATHER_THREADS]);

    // Wait for the row to land (acquire so plain ld.shared below is ordered).
    {
        uint32_t done;
        asm volatile(
            "{\n\t.reg .pred p;\n\t"
            "mbarrier.try_wait.parity.acquire.cta.shared::cta.b64 p, [%1], %2;\n\t"
            "selp.b32 %0, 1, 0, p;\n\t}"
            : "=r"(done) : "r"(mbar_sa), "r"(0u) : "memory");
        if (!done) {
            asm volatile(
                "{\n\t.reg .pred P1;\n\t"
                "WL_%=:\n\t"
                "mbarrier.try_wait.parity.acquire.cta.shared::cta.b64 P1, [%0], %1, 0x989680;\n\t"
                "@P1 bra.uni WD_%=;\n\t"
                "bra.uni WL_%=;\n\t"
                "WD_%=:\n\t}"
                :: "r"(mbar_sa), "r"(0u) : "memory");
        }
    }

    float2* __restrict__ o2 = reinterpret_cast<float2*>(out + (size_t)b * N_MOVES);

    float2 r0, r1, r2;
    r0.x = row[mp0.x] * __int_as_float(mp0.y);
    r0.y = row[mp0.z] * __int_as_float(mp0.w);
    r1.x = row[mp1.x] * __int_as_float(mp1.y);
    r1.y = row[mp1.z] * __int_as_float(mp1.w);
    r2.x = row[mp2.x] * __int_as_float(mp2.y);
    r2.y = row[mp2.z] * __int_as_float(mp2.w);
    __stcs(&o2[tid], r0);
    __stcs(&o2[tid + GATHER_THREADS], r1);
    __stcs(&o2[tid + 2 * GATHER_THREADS], r2);
    if (has3) {
        float2 r3;
        r3.x = row[mp3.x] * __int_as_float(mp3.y);
        r3.y = row[mp3.z] * __int_as_float(mp3.w);
        __stcs(&o2[tid + 3 * GATHER_THREADS], r3);
    }
}

// ---------------------------------------------------------------------------
extern "C" void kernel_launch(void* const* d_in, const int* in_sizes, int n_in,
                              void* d_out, int out_size) {
    const float* inputs = (const float*)d_in[0];   // [B, 80, 8, 8] = [B, 5120]
    const float* pmap   = (const float*)d_in[1];   // [5120, 1858]
    float* out          = (float*)d_out;           // [B, 1858]

    const int B = in_sizes[0] / C_IN;

    const int build_blocks = (TOTAL_V4 + V4_PER_BLOCK - 1) / V4_PER_BLOCK;  // 1162
    build_map_kernel<<<build_blocks, BUILD_THREADS>>>(
        reinterpret_cast<const float4*>(pmap));

    gather_kernel<<<B, GATHER_THREADS>>>(inputs, out);
}